// round 17
// baseline (speedup 1.0000x reference)
#include <cuda_runtime.h>
#include <cuda_fp16.h>

#define SH 72     // attn smem stride (halves)
#define STX 136   // x^T / We^T smem stride (halves)
#define STW 72    // weight^T smem stride (halves)
#define TST 136   // v-transpose buffer stride (halves)
#define NITEMS 800
#define NCTAS 296
typedef unsigned long long u64;
typedef unsigned int u32;

extern __shared__ char smem_raw[];

// Scratch (device globals; zero-init -> q pad rows are 0)
__device__ __half g_q[32 * 3136 * 64 + 8192];
__device__ __half g_k[32 * 3136 * 64];
__device__ __half g_vt[32 * 64 * 3136];
__device__ __half g_WeT[64 * 128];
__device__ __half g_WqT[192 * 64];
__device__ __half g_WpT[64 * 64];
__device__ __half g_W1T[64 * 64];
__device__ float  g_w2bar[64];
__device__ float  g_b2bar[1];
__device__ int    g_cnt[32];
__device__ int    g_qe;
__device__ int    g_qa;

// ---------- fp16 mma m16n8k16, fp32 accum ----------
__device__ __forceinline__ void mma_f16(float c[4], u32 a0, u32 a1, u32 a2, u32 a3,
                                        u32 b0, u32 b1) {
    asm volatile(
        "mma.sync.aligned.m16n8k16.row.col.f32.f16.f16.f32 "
        "{%0,%1,%2,%3}, {%4,%5,%6,%7}, {%8,%9}, {%0,%1,%2,%3};"
        : "+f"(c[0]), "+f"(c[1]), "+f"(c[2]), "+f"(c[3])
        : "r"(a0), "r"(a1), "r"(a2), "r"(a3), "r"(b0), "r"(b1));
}
__device__ __forceinline__ void ldm_x4(u32& r0, u32& r1, u32& r2, u32& r3, u32 saddr) {
    asm volatile("ldmatrix.sync.aligned.m8n8.x4.shared.b16 {%0,%1,%2,%3}, [%4];"
                 : "=r"(r0), "=r"(r1), "=r"(r2), "=r"(r3) : "r"(saddr));
}
__device__ __forceinline__ void cp16cg(u32 saddr, const void* gptr) {
    asm volatile("cp.async.cg.shared.global [%0], [%1], 16;"
                 :: "r"(saddr), "l"(gptr));
}
__device__ __forceinline__ u32 pack_h2(float lo, float hi) {
    __half2 h = __floats2half2_rn(lo, hi);
    return *(u32*)&h;
}
__device__ __forceinline__ u32 exp2_h2(float lo, float hi) {
    __half2 h = __floats2half2_rn(lo, hi);
    u32 r = *(u32*)&h;
    asm("ex2.approx.f16x2 %0, %0;" : "+r"(r));
    return r;
}
__device__ __forceinline__ u32 boffB(int lane, int ST) {
    int r = lane & 7, g = lane >> 3;
    return (u32)((((g >> 1) * 8 + r) * ST + (g & 1) * 8) * 2);
}
__device__ __forceinline__ u32 boffA(int lane, int ST) {
    int r = lane & 7, g = lane >> 3;
    return (u32)((((g & 1) * 8 + r) * ST + (g >> 1) * 8) * 2);
}

// =====================================================================
// Kernel 0: weight prep + queue/counter reset (every launch)
// =====================================================================
__global__ __launch_bounds__(256) void k_prep(
    const float* __restrict__ We, const float* __restrict__ Wqkv,
    const float* __restrict__ Wp, const float* __restrict__ W1,
    const float* __restrict__ W2, const float* __restrict__ bm2)
{
    int tid = blockIdx.x * 256 + threadIdx.x;
    int nthr = gridDim.x * 256;
    if (tid < 32) g_cnt[tid] = 0;
    if (tid == 32) g_qe = 0;
    if (tid == 33) g_qa = 0;
    for (int i = tid; i < 64 * 128; i += nthr) {
        int d = i >> 7, c = i & 127;
        g_WeT[d * 128 + c] = __float2half(We[c * 64 + d]);
    }
    for (int i = tid; i < 192 * 64; i += nthr) {
        int n = i >> 6, k = i & 63;
        g_WqT[n * 64 + k] = __float2half(Wqkv[k * 192 + n]);
    }
    for (int i = tid; i < 64 * 64; i += nthr) {
        int n = i >> 6, k = i & 63;
        g_WpT[n * 64 + k] = __float2half(Wp[k * 64 + n]);
        g_W1T[n * 64 + k] = __float2half(W1[k * 64 + n]);
    }
    int wi = tid >> 5, lane = tid & 31;
    if (wi < 64) {
        float s = W2[wi * 64 + lane] + W2[wi * 64 + 32 + lane];
#pragma unroll
        for (int o = 16; o > 0; o >>= 1)
            s += __shfl_xor_sync(0xffffffffu, s, o);
        if (lane == 0) g_w2bar[wi] = s * (1.0f / 64.0f);
    } else if (wi == 64) {
        float s = bm2[lane] + bm2[32 + lane];
#pragma unroll
        for (int o = 16; o > 0; o >>= 1)
            s += __shfl_xor_sync(0xffffffffu, s, o);
        if (lane == 0) g_b2bar[0] = s * (1.0f / 64.0f);
    }
}

// =====================================================================
// Fused persistent kernel (R16 + depth-2 cp.async, per-group interleave)
// =====================================================================
__global__ __launch_bounds__(256, 2) void k_fused(
    const float* __restrict__ x, const float* __restrict__ be,
    const float* __restrict__ g1, const float* __restrict__ b1,
    const float* __restrict__ g2, const float* __restrict__ b2,
    const float* __restrict__ bqkv,
    const float* __restrict__ bp, const float* __restrict__ gm,
    const float* __restrict__ bm, const float* __restrict__ bm1,
    float* __restrict__ out)
{
    __half* smh  = (__half*)smem_raw;
    int* ctrl = (int*)(smem_raw + 81920);

    const int tid  = threadIdx.x;
    const int lane = tid & 31;
    const int w    = tid >> 5;
    const int m0   = w * 16;
    const int qr   = lane >> 2;
    const int qc   = lane & 3;
    const u32 BONE = 0x3C003C00u;

    // ================== PHASE 1: embed + 2xLN + QKV (unchanged) ======
    {
        __half* sxt  = smh;                     // [128][STX], reused as vbuf
        __half* sWeT = sxt + 128 * STX;
        __half* sWqT = sWeT + 64 * STX;
        float*  sPar = (float*)(sWqT + 192 * STW);

        const u32 sxt_a  = (u32)__cvta_generic_to_shared(sxt)  + boffA(lane, STX);
        const u32 sWeT_b = (u32)__cvta_generic_to_shared(sWeT) + boffB(lane, STX);
        const u32 sWqT_b = (u32)__cvta_generic_to_shared(sWqT) + boffB(lane, STW);

        for (int i = tid; i < 64 * 64; i += 256) {
            int d = i >> 6, cp = i & 63;
            *(u32*)&sWeT[d * STX + cp * 2] = ((const u32*)g_WeT)[d * 64 + cp];
        }
        for (int i = tid; i < 192 * 32; i += 256) {
            int n = i >> 5, kp = i & 31;
            *(u32*)&sWqT[n * STW + kp * 2] = ((const u32*)g_WqT)[n * 32 + kp];
        }
        for (int i = tid; i < 64; i += 256) {
            sPar[i]       = be[i];
            sPar[64 + i]  = g1[i];
            sPar[128 + i] = b1[i];
            sPar[192 + i] = g2[i];
            sPar[256 + i] = b2[i];
        }
        for (int i = tid; i < 192; i += 256) sPar[320 + i] = bqkv[i];

        for (;;) {
            if (tid == 0) ctrl[0] = atomicAdd(&g_qe, 1);
            __syncthreads();
            int item = ctrl[0];
            if (item >= NITEMS) break;
            const int b  = item / 25;
            const int n0 = (item % 25) * 128;

            {
                const float* xb = x + (size_t)b * 128 * 3136;
                int j = tid & 127;
                bool ok = (n0 + j) < 3136;
                for (int c2 = (tid >> 7); c2 < 64; c2 += 2) {
                    int c = c2 * 2;
                    float v0 = ok ? xb[(size_t)c * 3136 + n0 + j] : 0.f;
                    float v1 = ok ? xb[(size_t)(c + 1) * 3136 + n0 + j] : 0.f;
                    *(u32*)&sxt[j * STX + c] = pack_h2(v0, v1);
                }
            }
            __syncthreads();

            float T[8][4];
#pragma unroll
            for (int nt = 0; nt < 8; nt++)
#pragma unroll
                for (int j = 0; j < 4; j++) T[nt][j] = 0.f;
#pragma unroll
            for (int kk = 0; kk < 8; kk++) {
                int k0 = kk * 16;
                u32 a0, a1, a2, a3;
                ldm_x4(a0, a1, a2, a3, sxt_a + (m0 * STX + k0) * 2);
#pragma unroll
                for (int ntp = 0; ntp < 4; ntp++) {
                    u32 b0, b1, b2, b3;
                    ldm_x4(b0, b1, b2, b3, sWeT_b + (ntp * 16 * STX + k0) * 2);
                    mma_f16(T[2 * ntp],     a0, a1, a2, a3, b0, b1);
                    mma_f16(T[2 * ntp + 1], a0, a1, a2, a3, b2, b3);
                }
            }
#pragma unroll
            for (int nt = 0; nt < 8; nt++) {
                int c0 = nt * 8 + 2 * qc;
                float be0 = sPar[c0], be1 = sPar[c0 + 1];
                T[nt][0] += be0; T[nt][1] += be1;
                T[nt][2] += be0; T[nt][3] += be1;
            }

#pragma unroll
            for (int pass = 0; pass < 2; pass++) {
                const float* gp = sPar + (pass == 0 ? 64 : 192);
                const float* bpp = sPar + (pass == 0 ? 128 : 256);
                float s1 = 0.f, s2 = 0.f, q1 = 0.f, q2 = 0.f;
#pragma unroll
                for (int nt = 0; nt < 8; nt++) {
                    s1 += T[nt][0] + T[nt][1];
                    q1 += T[nt][0] * T[nt][0] + T[nt][1] * T[nt][1];
                    s2 += T[nt][2] + T[nt][3];
                    q2 += T[nt][2] * T[nt][2] + T[nt][3] * T[nt][3];
                }
#pragma unroll
                for (int o = 1; o < 4; o <<= 1) {
                    s1 += __shfl_xor_sync(0xffffffffu, s1, o);
                    q1 += __shfl_xor_sync(0xffffffffu, q1, o);
                    s2 += __shfl_xor_sync(0xffffffffu, s2, o);
                    q2 += __shfl_xor_sync(0xffffffffu, q2, o);
                }
                float mu1 = s1 * (1.f / 64.f), mu2 = s2 * (1.f / 64.f);
                float r1 = rsqrtf(q1 * (1.f / 64.f) - mu1 * mu1 + 1e-5f);
                float r2 = rsqrtf(q2 * (1.f / 64.f) - mu2 * mu2 + 1e-5f);
#pragma unroll
                for (int nt = 0; nt < 8; nt++) {
                    int c0 = nt * 8 + 2 * qc;
                    float gg0 = gp[c0], gg1 = gp[c0 + 1];
                    float bb0 = bpp[c0], bb1 = bpp[c0 + 1];
                    T[nt][0] = (T[nt][0] - mu1) * r1 * gg0 + bb0;
                    T[nt][1] = (T[nt][1] - mu1) * r1 * gg1 + bb1;
                    T[nt][2] = (T[nt][2] - mu2) * r2 * gg0 + bb0;
                    T[nt][3] = (T[nt][3] - mu2) * r2 * gg1 + bb1;
                }
            }

            u32 ap[4][4];
#pragma unroll
            for (int kk = 0; kk < 4; kk++) {
                ap[kk][0] = pack_h2(T[2 * kk][0],     T[2 * kk][1]);
                ap[kk][1] = pack_h2(T[2 * kk][2],     T[2 * kk][3]);
                ap[kk][2] = pack_h2(T[2 * kk + 1][0], T[2 * kk + 1][1]);
                ap[kk][3] = pack_h2(T[2 * kk + 1][2], T[2 * kk + 1][3]);
            }

            const int t1 = n0 + m0 + qr;
            const int t2 = t1 + 8;
            const size_t tok1 = (size_t)b * 3136 + t1;
            const size_t tok2 = (size_t)b * 3136 + t2;
            const bool ok1 = t1 < 3136, ok2 = t2 < 3136;

#pragma unroll
            for (int p = 0; p < 3; p++) {
                float U[8][4];
#pragma unroll
                for (int nt = 0; nt < 8; nt++)
#pragma unroll
                    for (int j = 0; j < 4; j++) U[nt][j] = 0.f;
#pragma unroll
                for (int kk = 0; kk < 4; kk++) {
                    int k0 = kk * 16;
#pragma unroll
                    for (int ntp = 0; ntp < 4; ntp++) {
                        u32 b0, b1, b2, b3;
                        ldm_x4(b0, b1, b2, b3,
                               sWqT_b + ((p * 64 + ntp * 16) * STW + k0) * 2);
                        mma_f16(U[2 * ntp],     ap[kk][0], ap[kk][1], ap[kk][2], ap[kk][3], b0, b1);
                        mma_f16(U[2 * ntp + 1], ap[kk][0], ap[kk][1], ap[kk][2], ap[kk][3], b2, b3);
                    }
                }
#pragma unroll
                for (int nt = 0; nt < 8; nt++) {
                    int c0 = p * 64 + nt * 8 + 2 * qc;
                    float bb0 = sPar[320 + c0], bb1 = sPar[320 + c0 + 1];
                    U[nt][0] += bb0; U[nt][1] += bb1;
                    U[nt][2] += bb0; U[nt][3] += bb1;
                }
                if (p == 0) {
                    const float QS = 0.125f * 1.44269504088896f;
#pragma unroll
                    for (int nt = 0; nt < 8; nt++) {
                        int c0 = nt * 8 + 2 * qc;
                        if (ok1)
                            *(__half2*)(g_q + tok1 * 64 + c0) =
                                __floats2half2_rn(U[nt][0] * QS, U[nt][1] * QS);
                        if (ok2)
                            *(__half2*)(g_q + tok2 * 64 + c0) =
                                __floats2half2_rn(U[nt][2] * QS, U[nt][3] * QS);
                    }
                } else if (p == 1) {
#pragma unroll
                    for (int nt = 0; nt < 8; nt++) {
                        int c0 = nt * 8 + 2 * qc;
                        if (ok1)
                            *(__half2*)(g_k + tok1 * 64 + c0) =
                                __floats2half2_rn(U[nt][0], U[nt][1]);
                        if (ok2)
                            *(__half2*)(g_k + tok2 * 64 + c0) =
                                __floats2half2_rn(U[nt][2], U[nt][3]);
                    }
                } else {
                    __half* vbuf = sxt;
                    __syncthreads();
#pragma unroll
                    for (int nt = 0; nt < 8; nt++) {
                        int c0 = nt * 8 + 2 * qc;
                        int lt1 = m0 + qr, lt2 = lt1 + 8;
                        vbuf[c0 * TST + lt1]       = __float2half(U[nt][0]);
                        vbuf[(c0 + 1) * TST + lt1] = __float2half(U[nt][1]);
                        vbuf[c0 * TST + lt2]       = __float2half(U[nt][2]);
                        vbuf[(c0 + 1) * TST + lt2] = __float2half(U[nt][3]);
                    }
                    __syncthreads();
                    int d = tid >> 2, ch = (tid & 3) * 32;
                    if (n0 + ch < 3136) {
                        __half* dst = g_vt + ((size_t)b * 64 + d) * 3136 + n0 + ch;
                        const __half* src = vbuf + d * TST + ch;
#pragma unroll
                        for (int j = 0; j < 4; j++) {
                            __half2 h0 = *(const __half2*)(src + j * 8);
                            __half2 h1 = *(const __half2*)(src + j * 8 + 2);
                            __half2 h2 = *(const __half2*)(src + j * 8 + 4);
                            __half2 h3 = *(const __half2*)(src + j * 8 + 6);
                            uint4 v;
                            v.x = *(u32*)&h0; v.y = *(u32*)&h1;
                            v.z = *(u32*)&h2; v.w = *(u32*)&h3;
                            *(uint4*)(dst + j * 8) = v;
                        }
                    }
                }
            }
            __threadfence();
            __syncthreads();
            if (tid == 0) atomicAdd(&g_cnt[b], 1);
        }
    }
    __syncthreads();

    // ================== PHASE 2: flash attn + fused MLP ==============
    {
        __half* sk  = smh;                        // [3][64][SH]
        __half* svt = smh + 3 * 64 * SH;          // [3][64][SH]
        __half* sWp = smh + 6 * 64 * SH;          // [64][STW]
        __half* sW1 = sWp + 64 * STW;             // [64][STW]
        float*  sPar = (float*)(sW1 + 64 * STW);

        const u32 bB_sh = boffB(lane, SH);
        u32 skb[3], svb[3];
        __half* skp[3];
        __half* svp[3];
#pragma unroll
        for (int i = 0; i < 3; i++) {
            skp[i] = sk + i * 64 * SH;
            svp[i] = svt + i * 64 * SH;
            skb[i] = (u32)__cvta_generic_to_shared(skp[i]) + bB_sh;
            svb[i] = (u32)__cvta_generic_to_shared(svp[i]) + bB_sh;
        }
        const u32 sWp_b = (u32)__cvta_generic_to_shared(sWp) + boffB(lane, STW);
        const u32 sW1_b = (u32)__cvta_generic_to_shared(sW1) + boffB(lane, STW);

        for (int i = tid; i < 64 * 32; i += 256) {
            int n = i >> 5, kp = i & 31;
            *(u32*)&sWp[n * STW + kp * 2] = ((const u32*)g_WpT)[n * 32 + kp];
            *(u32*)&sW1[n * STW + kp * 2] = ((const u32*)g_W1T)[n * 32 + kp];
        }
        for (int i = tid; i < 64; i += 256) {
            sPar[i]       = bp[i];
            sPar[64 + i]  = gm[i];
            sPar[128 + i] = bm[i];
            sPar[192 + i] = bm1[i];
            sPar[256 + i] = g_w2bar[i];
        }
        if (tid == 0) sPar[320] = g_b2bar[0];

        for (;;) {
            if (tid == 0) ctrl[0] = atomicAdd(&g_qa, 1);
            __syncthreads();
            int item = ctrl[0];
            if (item >= NITEMS) break;
            const int b   = item / 25;
            const int nq0 = (item % 25) * 128;

            if (tid == 0) {
                while (atomicAdd(&g_cnt[b], 0) < 25) { __nanosleep(128); }
            }
            __syncthreads();
            __threadfence();

            u32 aq[4][4];
            {
                const __half* q0 = g_q + (size_t)(b * 3136 + nq0 + m0 + qr) * 64;
                const __half* q8 = q0 + 8 * 64;
#pragma unroll
                for (int kk = 0; kk < 4; kk++) {
                    aq[kk][0] = *(const u32*)(q0 + kk * 16 + 2 * qc);
                    aq[kk][1] = *(const u32*)(q8 + kk * 16 + 2 * qc);
                    aq[kk][2] = *(const u32*)(q0 + kk * 16 + 8 + 2 * qc);
                    aq[kk][3] = *(const u32*)(q8 + kk * 16 + 8 + 2 * qc);
                }
            }

            const __half* kbase  = g_k  + (size_t)b * 3136 * 64;
            const __half* vtbase = g_vt + (size_t)b * 64 * 3136;

            // ---- prefetch tiles 0 and 1 (separate commit groups) ----
#pragma unroll
            for (int pf = 0; pf < 2; pf++) {
                const __half* kt  = kbase  + (size_t)pf * 64 * 64;
                const __half* vtt = vtbase + (size_t)pf * 64;
#pragma unroll
                for (int i = 0; i < 2; i++) {
                    int c = tid + i * 256;
                    int r = c >> 3, ch = c & 7;
                    u32 dk = (u32)__cvta_generic_to_shared(skp[pf] + r * SH + ch * 8);
                    u32 dv = (u32)__cvta_generic_to_shared(svp[pf] + r * SH + ch * 8);
                    cp16cg(dk, kt + r * 64 + ch * 8);
                    cp16cg(dv, vtt + (size_t)r * 3136 + ch * 8);
                }
                asm volatile("cp.async.commit_group;");
            }

            float O[8][4];
#pragma unroll
            for (int nt = 0; nt < 8; nt++)
#pragma unroll
                for (int j = 0; j < 4; j++) O[nt][j] = 0.f;
            float la[4] = {0.f, 0.f, 0.f, 0.f};

            int cur = 0, pfb = 2;   // rotating buffer indices
            for (int t = 0; t < 49; ++t) {
                if (t < 48) { asm volatile("cp.async.wait_group 1;"); }
                else        { asm volatile("cp.async.wait_group 0;"); }
                __syncthreads();

                if (t + 2 < 49) {   // prefetch t+2 into pfb
                    const __half* kt  = kbase  + (size_t)(t + 2) * 64 * 64;
                    const __half* vtt = vtbase + (size_t)(t + 2) * 64;
#pragma unroll
                    for (int i = 0; i < 2; i++) {
                        int c = tid + i * 256;
                        int r = c >> 3, ch = c & 7;
                        u32 dk = (u32)__cvta_generic_to_shared(skp[pfb] + r * SH + ch * 8);
                        u32 dv = (u32)__cvta_generic_to_shared(svp[pfb] + r * SH + ch * 8);
                        cp16cg(dk, kt + r * 64 + ch * 8);
                        cp16cg(dv, vtt + (size_t)r * 3136 + ch * 8);
                    }
                    asm volatile("cp.async.commit_group;");
                }

                const u32 skc_b  = skb[cur];
                const u32 svtc_b = svb[cur];

                // ---- per-group interleave: S(g) -> exp2 -> ones -> PV(g) ----
#pragma unroll
                for (int g = 0; g < 4; g++) {
                    float Sg[2][4];
#pragma unroll
                    for (int j = 0; j < 4; j++) { Sg[0][j] = 0.f; Sg[1][j] = 0.f; }
#pragma unroll
                    for (int kk = 0; kk < 4; kk++) {
                        u32 b0, b1, b2, b3;
                        ldm_x4(b0, b1, b2, b3, skc_b + (g * 16 * SH + kk * 16) * 2);
                        mma_f16(Sg[0], aq[kk][0], aq[kk][1], aq[kk][2], aq[kk][3], b0, b1);
                        mma_f16(Sg[1], aq[kk][0], aq[kk][1], aq[kk][2], aq[kk][3], b2, b3);
                    }
                    u32 pg0 = exp2_h2(Sg[0][0], Sg[0][1]);
                    u32 pg1 = exp2_h2(Sg[0][2], Sg[0][3]);
                    u32 pg2 = exp2_h2(Sg[1][0], Sg[1][1]);
                    u32 pg3 = exp2_h2(Sg[1][2], Sg[1][3]);
                    mma_f16(la, pg0, pg1, pg2, pg3, BONE, BONE);
#pragma unroll
                    for (int ntp = 0; ntp < 4; ntp++) {
                        u32 b0, b1, b2, b3;
                        ldm_x4(b0, b1, b2, b3, svtc_b + (ntp * 16 * SH + g * 16) * 2);
                        mma_f16(O[2 * ntp],     pg0, pg1, pg2, pg3, b0, b1);
                        mma_f16(O[2 * ntp + 1], pg0, pg1, pg2, pg3, b2, b3);
                    }
                }

                cur = (cur == 2) ? 0 : cur + 1;
                pfb = (pfb == 2) ? 0 : pfb + 1;
            }

            // ---- fused epilogue (la[0]/la[2] lane-uniform row sums) ----
            float inv1 = 1.0f / la[0], inv2 = 1.0f / la[2];

            u32 af[4][4];
#pragma unroll
            for (int kk = 0; kk < 4; kk++) {
                af[kk][0] = pack_h2(O[2 * kk][0] * inv1,     O[2 * kk][1] * inv1);
                af[kk][1] = pack_h2(O[2 * kk][2] * inv2,     O[2 * kk][3] * inv2);
                af[kk][2] = pack_h2(O[2 * kk + 1][0] * inv1, O[2 * kk + 1][1] * inv1);
                af[kk][3] = pack_h2(O[2 * kk + 1][2] * inv2, O[2 * kk + 1][3] * inv2);
            }

            float U[8][4];
#pragma unroll
            for (int nt = 0; nt < 8; nt++)
#pragma unroll
                for (int j = 0; j < 4; j++) U[nt][j] = 0.f;
#pragma unroll
            for (int kk = 0; kk < 4; kk++) {
                int k0 = kk * 16;
#pragma unroll
                for (int ntp = 0; ntp < 4; ntp++) {
                    u32 b0, b1, b2, b3;
                    ldm_x4(b0, b1, b2, b3, sWp_b + (ntp * 16 * STW + k0) * 2);
                    mma_f16(U[2 * ntp],     af[kk][0], af[kk][1], af[kk][2], af[kk][3], b0, b1);
                    mma_f16(U[2 * ntp + 1], af[kk][0], af[kk][1], af[kk][2], af[kk][3], b2, b3);
                }
            }
#pragma unroll
            for (int nt = 0; nt < 8; nt++) {
                int c0 = nt * 8 + 2 * qc;
                U[nt][0] += sPar[c0]; U[nt][1] += sPar[c0 + 1];
                U[nt][2] += sPar[c0]; U[nt][3] += sPar[c0 + 1];
            }

            {
                float s1 = 0.f, s2 = 0.f, q1 = 0.f, q2 = 0.f;
#pragma unroll
                for (int nt = 0; nt < 8; nt++) {
                    s1 += U[nt][0] + U[nt][1];
                    q1 += U[nt][0] * U[nt][0] + U[nt][1] * U[nt][1];
                    s2 += U[nt][2] + U[nt][3];
                    q2 += U[nt][2] * U[nt][2] + U[nt][3] * U[nt][3];
                }
#pragma unroll
                for (int o = 1; o < 4; o <<= 1) {
                    s1 += __shfl_xor_sync(0xffffffffu, s1, o);
                    q1 += __shfl_xor_sync(0xffffffffu, q1, o);
                    s2 += __shfl_xor_sync(0xffffffffu, s2, o);
                    q2 += __shfl_xor_sync(0xffffffffu, q2, o);
                }
                float mu1 = s1 * (1.f / 64.f), mu2 = s2 * (1.f / 64.f);
                float r1 = rsqrtf(q1 * (1.f / 64.f) - mu1 * mu1 + 1e-5f);
                float r2 = rsqrtf(q2 * (1.f / 64.f) - mu2 * mu2 + 1e-5f);
#pragma unroll
                for (int nt = 0; nt < 8; nt++) {
                    int c0 = nt * 8 + 2 * qc;
                    float gg0 = sPar[64 + c0], gg1 = sPar[64 + c0 + 1];
                    float bb0 = sPar[128 + c0], bb1 = sPar[128 + c0 + 1];
                    U[nt][0] = (U[nt][0] - mu1) * r1 * gg0 + bb0;
                    U[nt][1] = (U[nt][1] - mu1) * r1 * gg1 + bb1;
                    U[nt][2] = (U[nt][2] - mu2) * r2 * gg0 + bb0;
                    U[nt][3] = (U[nt][3] - mu2) * r2 * gg1 + bb1;
                }
            }

            u32 uf[4][4];
#pragma unroll
            for (int kk = 0; kk < 4; kk++) {
                uf[kk][0] = pack_h2(U[2 * kk][0],     U[2 * kk][1]);
                uf[kk][1] = pack_h2(U[2 * kk][2],     U[2 * kk][3]);
                uf[kk][2] = pack_h2(U[2 * kk + 1][0], U[2 * kk + 1][1]);
                uf[kk][3] = pack_h2(U[2 * kk + 1][2], U[2 * kk + 1][3]);
            }
            float H[8][4];
#pragma unroll
            for (int nt = 0; nt < 8; nt++)
#pragma unroll
                for (int j = 0; j < 4; j++) H[nt][j] = 0.f;
#pragma unroll
            for (int kk = 0; kk < 4; kk++) {
                int k0 = kk * 16;
#pragma unroll
                for (int ntp = 0; ntp < 4; ntp++) {
                    u32 b0, b1, b2, b3;
                    ldm_x4(b0, b1, b2, b3, sW1_b + (ntp * 16 * STW + k0) * 2);
                    mma_f16(H[2 * ntp],     uf[kk][0], uf[kk][1], uf[kk][2], uf[kk][3], b0, b1);
                    mma_f16(H[2 * ntp + 1], uf[kk][0], uf[kk][1], uf[kk][2], uf[kk][3], b2, b3);
                }
            }
#pragma unroll
            for (int nt = 0; nt < 8; nt++) {
                int c0 = nt * 8 + 2 * qc;
                float bb0 = sPar[192 + c0], bb1 = sPar[192 + c0 + 1];
                float v;
                v = H[nt][0] + bb0; H[nt][0] = 0.5f * v * (1.0f + erff(v * 0.70710678118654752f));
                v = H[nt][1] + bb1; H[nt][1] = 0.5f * v * (1.0f + erff(v * 0.70710678118654752f));
                v = H[nt][2] + bb0; H[nt][2] = 0.5f * v * (1.0f + erff(v * 0.70710678118654752f));
                v = H[nt][3] + bb1; H[nt][3] = 0.5f * v * (1.0f + erff(v * 0.70710678118654752f));
            }

            float s1 = 0.f, s2 = 0.f;
#pragma unroll
            for (int nt = 0; nt < 8; nt++) {
                int c0 = nt * 8 + 2 * qc;
                float w0 = sPar[256 + c0], w1v = sPar[256 + c0 + 1];
                s1 += H[nt][0] * w0 + H[nt][1] * w1v;
                s2 += H[nt][2] * w0 + H[nt][3] * w1v;
            }
#pragma unroll
            for (int o = 1; o < 4; o <<= 1) {
                s1 += __shfl_xor_sync(0xffffffffu, s1, o);
                s2 += __shfl_xor_sync(0xffffffffu, s2, o);
            }
            if (qc == 0) {
                float bb = sPar[320];
                int o1 = nq0 + m0 + qr, o2 = o1 + 8;
                if (o1 < 3136) out[(size_t)b * 3136 + o1] = s1 + bb;
                if (o2 < 3136) out[(size_t)b * 3136 + o2] = s2 + bb;
            }
        }
    }
}

// =====================================================================
extern "C" void kernel_launch(void* const* d_in, const int* in_sizes, int n_in,
                              void* d_out, int out_size)
{
    const float* x    = (const float*)d_in[0];
    const float* We   = (const float*)d_in[1];
    const float* be   = (const float*)d_in[2];
    const float* g1   = (const float*)d_in[3];
    const float* b1   = (const float*)d_in[4];
    const float* g2   = (const float*)d_in[5];
    const float* b2   = (const float*)d_in[6];
    const float* Wqkv = (const float*)d_in[7];
    const float* bqkv = (const float*)d_in[8];
    const float* Wp   = (const float*)d_in[9];
    const float* bp   = (const float*)d_in[10];
    const float* gm   = (const float*)d_in[11];
    const float* bm   = (const float*)d_in[12];
    const float* W1   = (const float*)d_in[13];
    const float* bm1  = (const float*)d_in[14];
    const float* W2   = (const float*)d_in[15];
    const float* bm2  = (const float*)d_in[16];
    float* out = (float*)d_out;

    const int SMF = 81920 + 32;

    (void)cudaFuncSetAttribute(k_fused, cudaFuncAttributeMaxDynamicSharedMemorySize, SMF);

    k_prep<<<32, 256>>>(We, Wqkv, Wp, W1, W2, bm2);
    k_fused<<<NCTAS, 256, SMF>>>(x, be, g1, b1, g2, b2, bqkv,
                                 bp, gm, bm, bm1, out);
}